// round 10
// baseline (speedup 1.0000x reference)
#include <cuda_runtime.h>
#include <cuda_bf16.h>
#include <mma.h>
using namespace nvcuda;

#define NMAX 50000
#define EMAX 500000
#define NPAD (NMAX + 128)

typedef unsigned long long u64;
typedef __nv_bfloat16 bf16;

// ---------------- device scratch (static allocations, allowed) --------------
__device__ float g_qkv [(size_t)NMAX * 384];    // Q|K|V fp32 (attention input)
__device__ float g_buf1[(size_t)NMAX * 128];    // h1 fp32 (residual for FFN2)
__device__ float g_b1fold[256];                 // b1 + sh1^T W1

__device__ __align__(16) bf16 g_xh  [(size_t)NPAD * 128];
__device__ __align__(16) bf16 g_xl  [(size_t)NPAD * 128];
__device__ __align__(16) bf16 g_aggh[(size_t)NPAD * 128];
__device__ __align__(16) bf16 g_aggl[(size_t)NPAD * 128];
__device__ __align__(16) bf16 g_b1h [(size_t)NPAD * 128];
__device__ __align__(16) bf16 g_b1l [(size_t)NPAD * 128];
__device__ __align__(16) bf16 g_b2h [(size_t)NPAD * 256];
__device__ __align__(16) bf16 g_b2l [(size_t)NPAD * 256];
__device__ __align__(16) bf16 g_wqkvh[128 * 384];
__device__ __align__(16) bf16 g_wqkvl[128 * 384];
__device__ __align__(16) bf16 g_woh [128 * 128];
__device__ __align__(16) bf16 g_wol [128 * 128];
__device__ __align__(16) bf16 g_w1h [128 * 256];
__device__ __align__(16) bf16 g_w1l [128 * 256];
__device__ __align__(16) bf16 g_w2h [256 * 128];
__device__ __align__(16) bf16 g_w2l [256 * 128];

__device__ int   g_cnt   [NMAX];
__device__ int   g_rp    [NMAX + 1];
__device__ int   g_cursor[NMAX];
__device__ int   g_srcs  [EMAX];
__device__ int   g_bsum  [256];
__device__ int   g_is64;
__device__ float g_red[512];
__device__ float g_aff[512];

__device__ __forceinline__ bf16* bfptr(int id) {
    switch (id) {
        case 0:  return g_xh;    case 1:  return g_xl;
        case 2:  return g_aggh;  case 3:  return g_aggl;
        case 4:  return g_b1h;   case 5:  return g_b1l;
        case 6:  return g_b2h;   case 7:  return g_b2l;
        case 8:  return g_wqkvh; case 9:  return g_wqkvl;
        case 10: return g_woh;   case 11: return g_wol;
        case 12: return g_w1h;   case 13: return g_w1l;
        case 14: return g_w2h;   case 15: return g_w2l;
    }
    return 0;
}

__device__ __forceinline__ float* fbptr(int id) {
    switch (id) {
        case 0: return g_qkv;
        case 1: return g_buf1;
        case 2: return g_b1fold;
    }
    return 0;
}

__device__ __forceinline__ int edge_at(const void* ei, size_t idx) {
    if (g_is64) return (int)((const long long*)ei)[idx];
    return ((const int*)ei)[idx];
}

union BF4 { bf16 b[4]; u64 uu; };
union BF8 { bf16 b[8]; uint4 u4; };

__device__ __forceinline__ void cp16(void* smem, const void* gmem) {
    unsigned sa = (unsigned)__cvta_generic_to_shared(smem);
    asm volatile("cp.async.cg.shared.global [%0], [%1], 16;\n" :: "r"(sa), "l"(gmem));
}
#define CP_COMMIT() asm volatile("cp.async.commit_group;\n" ::: "memory")
#define CP_WAIT0()  asm volatile("cp.async.wait_group 0;\n" ::: "memory")
#define CP_WAIT2()  asm volatile("cp.async.wait_group 2;\n" ::: "memory")

// dynamic smem layout for 4-stage pipeline (bytes)
#define SMEM_AH 0
#define SMEM_AL 24576
#define SMEM_WH 49152
#define SMEM_WL 66560
#define SMEM_BYTES 83968
#define AIDX(s, r, c) ((s) * 3072 + (r) * 24 + (c))
#define WIDX(s, r, c) ((s) * 2176 + (r) * 136 + (c))

__global__ __launch_bounds__(256) void pgemm(
    int AHid, int WHid, int Wld,
    float* Cext, int Cid, int CHid,
    int nrows, int K, int ldc,
    const float* biasExt, int biasId,
    const float* Rext, int rid, int hasResid, int ldres, int rscSlot,
    int doRelu, int statsSlot);

// --------------------- streams/events + smem attr (static init) --------------
static cudaStream_t g_s2;
static cudaEvent_t  g_e1, g_e2;
static struct StreamInit {
    StreamInit() {
        cudaStreamCreateWithFlags(&g_s2, cudaStreamNonBlocking);
        cudaEventCreateWithFlags(&g_e1, cudaEventDisableTiming);
        cudaEventCreateWithFlags(&g_e2, cudaEventDisableTiming);
        cudaFuncSetAttribute(pgemm, cudaFuncAttributeMaxDynamicSharedMemorySize, SMEM_BYTES);
    }
} g_streamInit;

// ---------------------------- small kernels ---------------------------------
__global__ void k_init(const void* ei, int e, int n) {
    int i = blockIdx.x * blockDim.x + threadIdx.x;
    if (blockIdx.x == 0) {
        const long long* p = (const long long*)ei;
        int m = e < 256 ? e : 256;
        int bad = 0;
        if (threadIdx.x < m) {
            long long v = p[threadIdx.x];
            bad = (v < 0 || v >= NMAX);
        }
        int any = __syncthreads_or(bad);
        if (threadIdx.x == 0) g_is64 = !any;
    }
    if (i < n)   g_cnt[i] = 0;
    if (i < 512) g_red[i] = 0.f;
}

__device__ __forceinline__ void splitw(float v, bf16* ph, bf16* pl) {
    bf16 h = __float2bfloat16(v);
    *ph = h;
    *pl = __float2bfloat16(v - __bfloat162float(h));
}

// merged: x hi/lo split + all weight splits (one launch)
__global__ void k_prep(const float* __restrict__ x, int total4,
                       const float* __restrict__ WQ, const float* __restrict__ WK,
                       const float* __restrict__ WV, const float* __restrict__ WO,
                       const float* __restrict__ W2) {
    int i = blockIdx.x * blockDim.x + threadIdx.x;
    if (i < total4) {
        float4 v = *(const float4*)(x + i * 4);
        float vv[4] = {v.x, v.y, v.z, v.w};
        BF4 h, l;
#pragma unroll
        for (int j = 0; j < 4; j++) {
            bf16 hh = __float2bfloat16(vv[j]);
            h.b[j] = hh;
            l.b[j] = __float2bfloat16(vv[j] - __bfloat162float(hh));
        }
        *(u64*)(g_xh + i * 4) = h.uu;
        *(u64*)(g_xl + i * 4) = l.uu;
    }
    if (i < 16384) {
        int k = i >> 7, m = i & 127;
        splitw(WQ[i], &g_wqkvh[k * 384 + m],       &g_wqkvl[k * 384 + m]);
        splitw(WK[i], &g_wqkvh[k * 384 + 128 + m], &g_wqkvl[k * 384 + 128 + m]);
        splitw(WV[i], &g_wqkvh[k * 384 + 256 + m], &g_wqkvl[k * 384 + 256 + m]);
    } else if (i < 32768) {
        int j = i - 16384;
        splitw(WO[j], &g_woh[j], &g_wol[j]);
    } else if (i < 65536) {
        int j = i - 32768;
        splitw(W2[j], &g_w2h[j], &g_w2l[j]);
    }
}

__global__ void k_hist(const void* ei, int e) {
    int i = blockIdx.x * blockDim.x + threadIdx.x;
    if (i < e) atomicAdd(&g_cnt[edge_at(ei, (size_t)e + i)], 1);
}

__global__ void k_scan1(int n) {
    __shared__ int sh[1024];
    int t = threadIdx.x;
    int idx = blockIdx.x * 1024 + t;
    int v = (idx < n) ? g_cnt[idx] : 0;
    sh[t] = v;
    __syncthreads();
    for (int off = 1; off < 1024; off <<= 1) {
        int add = (t >= off) ? sh[t - off] : 0;
        __syncthreads();
        sh[t] += add;
        __syncthreads();
    }
    if (idx < n) g_rp[idx] = sh[t] - v;
    if (t == 1023) g_bsum[blockIdx.x] = sh[1023];
}

__global__ void k_scan2(int nb) {
    if (threadIdx.x == 0) {
        int run = 0;
        for (int i = 0; i < nb; i++) { int c = g_bsum[i]; g_bsum[i] = run; run += c; }
    }
}

__global__ void k_scan3(int n, int e) {
    int idx = blockIdx.x * 1024 + threadIdx.x;
    if (idx < n) {
        int v = g_rp[idx] + g_bsum[blockIdx.x];
        g_rp[idx] = v;
        g_cursor[idx] = v;
    }
    if (idx == 0) g_rp[n] = e;
}

__global__ void k_scatter(const void* ei, int e) {
    int i = blockIdx.x * blockDim.x + threadIdx.x;
    if (i < e) {
        int d = edge_at(ei, (size_t)e + i);
        int s = edge_at(ei, (size_t)i);
        int p = atomicAdd(&g_cursor[d], 1);
        g_srcs[p] = s;
    }
}

// ---------------- attention: one warp per destination node ------------------
__global__ void k_attn(int n) {
    int warp = (blockIdx.x * blockDim.x + threadIdx.x) >> 5;
    int lane = threadIdx.x & 31;
    if (warp >= n) return;

    float4 q = *(const float4*)(g_qkv + (size_t)warp * 384 + lane * 4);

    float ax = 0.f, ay = 0.f, az = 0.f, aw = 0.f, se = 0.f;
    int beg = g_rp[warp], end = g_rp[warp + 1];

    int p = beg;
    int ja = (p     < end) ? g_srcs[p]     : -1;
    int jb = (p + 1 < end) ? g_srcs[p + 1] : -1;
    float4 ka = make_float4(0.f, 0.f, 0.f, 0.f), va = ka, kb = ka, vb = ka;
    if (ja >= 0) {
        const float* b = g_qkv + (size_t)ja * 384;
        ka = *(const float4*)(b + 128 + lane * 4);
        va = *(const float4*)(b + 256 + lane * 4);
    }
    if (jb >= 0) {
        const float* b = g_qkv + (size_t)jb * 384;
        kb = *(const float4*)(b + 128 + lane * 4);
        vb = *(const float4*)(b + 256 + lane * 4);
    }

    while (ja >= 0) {
        int jc = (p + 2 < end) ? g_srcs[p + 2] : -1;
        int jd = (p + 3 < end) ? g_srcs[p + 3] : -1;
        float4 kc = make_float4(0.f, 0.f, 0.f, 0.f), vc = kc, kd = kc, vd = kc;
        if (jc >= 0) {
            const float* b = g_qkv + (size_t)jc * 384;
            kc = *(const float4*)(b + 128 + lane * 4);
            vc = *(const float4*)(b + 256 + lane * 4);
        }
        if (jd >= 0) {
            const float* b = g_qkv + (size_t)jd * 384;
            kd = *(const float4*)(b + 128 + lane * 4);
            vd = *(const float4*)(b + 256 + lane * 4);
        }

        float m1 = (jb >= 0) ? 1.f : 0.f;
        float s0 = q.x * ka.x + q.y * ka.y + q.z * ka.z + q.w * ka.w;
        float s1 = q.x * kb.x + q.y * kb.y + q.z * kb.z + q.w * kb.w;
        s0 += __shfl_xor_sync(0xffffffffu, s0, 1);
        s1 += __shfl_xor_sync(0xffffffffu, s1, 1);
        s0 += __shfl_xor_sync(0xffffffffu, s0, 2);
        s1 += __shfl_xor_sync(0xffffffffu, s1, 2);
        s0 = fminf(fmaxf(s0 * 0.25f, -5.f), 5.f);
        s1 = fminf(fmaxf(s1 * 0.25f, -5.f), 5.f);
        float e0 = __expf(s0);
        float e1 = __expf(s1) * m1;
        ax += e0 * va.x + e1 * vb.x;
        ay += e0 * va.y + e1 * vb.y;
        az += e0 * va.z + e1 * vb.z;
        aw += e0 * va.w + e1 * vb.w;
        se += e0 + e1;

        ja = jc; ka = kc; va = vc;
        jb = jd; kb = kd; vb = vd;
        p += 2;
    }

    float inv = 1.0f / (se + 1e-16f);
    float o[4] = {ax * inv, ay * inv, az * inv, aw * inv};
    BF4 oh, ol;
#pragma unroll
    for (int j = 0; j < 4; j++) {
        bf16 h = __float2bfloat16(o[j]);
        oh.b[j] = h;
        ol.b[j] = __float2bfloat16(o[j] - __bfloat162float(h));
    }
    *(u64*)(g_aggh + (size_t)warp * 128 + lane * 4) = oh.uu;
    *(u64*)(g_aggl + (size_t)warp * 128 + lane * 4) = ol.uu;
}

// ------ tensor-core GEMM: bf16 3-term split, 4-stage cp.async pipeline ------
__global__ __launch_bounds__(256) void pgemm(
    int AHid, int WHid, int Wld,
    float* Cext, int Cid, int CHid,
    int nrows, int K, int ldc,
    const float* biasExt, int biasId,
    const float* Rext, int rid, int hasResid, int ldres, int rscSlot,
    int doRelu, int statsSlot)
{
    extern __shared__ __align__(16) char dsm[];
    bf16* AsH = (bf16*)(dsm + SMEM_AH);
    bf16* AsL = (bf16*)(dsm + SMEM_AL);
    bf16* WsH = (bf16*)(dsm + SMEM_WH);
    bf16* WsL = (bf16*)(dsm + SMEM_WL);
    float* Cs = (float*)dsm;                 // epilogue scratch (aliases stages)
    __shared__ float sSum[128], sSq[128];

    const bf16* AH = bfptr(AHid);
    const bf16* AL = bfptr(AHid + 1);
    const bf16* WH = bfptr(WHid);
    const bf16* WL = bfptr(WHid + 1);
    float* C = (Cid >= 0) ? fbptr(Cid) : Cext;
    bf16* CH = (CHid >= 0) ? bfptr(CHid) : 0;
    bf16* CL = (CHid >= 0) ? bfptr(CHid + 1) : 0;
    const float* bias = (biasId >= 0) ? fbptr(biasId) : biasExt;
    const float* resid = hasResid ? ((rid >= 0) ? fbptr(rid) : Rext) : 0;

    int tid  = threadIdx.x;
    int warp = tid >> 5;
    int lane = tid & 31;
    int rowBase = blockIdx.x * 128;
    int colBase = blockIdx.y * 128;

    int wRow = (warp >> 2) * 64;
    int wCol = (warp & 3) * 32;

    if (statsSlot >= 0 && tid < 128) { sSum[tid] = 0.f; sSq[tid] = 0.f; }

    int ar = tid >> 1;
    int ak = (tid & 1) * 8;
    int wr = tid >> 4;
    int wc = (tid & 15) * 8;

    wmma::fragment<wmma::accumulator, 16, 16, 16, float> acc[4][2];
#pragma unroll
    for (int i = 0; i < 4; i++)
#pragma unroll
        for (int j = 0; j < 2; j++) wmma::fill_fragment(acc[i][j], 0.f);

    const size_t aOff = (size_t)(rowBase + ar) * K + ak;

#define STAGE_LOAD(s, k0)                                                      \
    do {                                                                       \
        cp16(&AsH[AIDX(s, ar, ak)], AH + aOff + (k0));                         \
        cp16(&AsL[AIDX(s, ar, ak)], AL + aOff + (k0));                         \
        cp16(&WsH[WIDX(s, wr, wc)], WH + (size_t)((k0) + wr) * Wld + colBase + wc); \
        cp16(&WsL[WIDX(s, wr, wc)], WL + (size_t)((k0) + wr) * Wld + colBase + wc); \
    } while (0)

    // prologue: commit 3 stages ahead (nIter >= 8 always)
    STAGE_LOAD(0, 0);  CP_COMMIT();
    STAGE_LOAD(1, 16); CP_COMMIT();
    STAGE_LOAD(2, 32); CP_COMMIT();

    int nIter = K >> 4;
    for (int it = 0; it < nIter; it++) {
        int st = it & 3;
        CP_WAIT2();               // oldest of 3 outstanding groups (stage it) done
        __syncthreads();          // also fences compute(it-1) before buffer reuse

        int kn = (it + 3) << 4;
        if (kn < K) STAGE_LOAD((it + 3) & 3, kn);
        CP_COMMIT();              // empty group keeps outstanding-count invariant

        wmma::fragment<wmma::matrix_a, 16, 16, 16, bf16, wmma::row_major> aH[4], aL[4];
        wmma::fragment<wmma::matrix_b, 16, 16, 16, bf16, wmma::row_major> bH[2], bL[2];
#pragma unroll
        for (int mi = 0; mi < 4; mi++) {
            wmma::load_matrix_sync(aH[mi], &AsH[AIDX(st, wRow + mi * 16, 0)], 24);
            wmma::load_matrix_sync(aL[mi], &AsL[AIDX(st, wRow + mi * 16, 0)], 24);
        }
#pragma unroll
        for (int ni = 0; ni < 2; ni++) {
            wmma::load_matrix_sync(bH[ni], &WsH[WIDX(st, 0, wCol + ni * 16)], 136);
            wmma::load_matrix_sync(bL[ni], &WsL[WIDX(st, 0, wCol + ni * 16)], 136);
        }
#pragma unroll
        for (int mi = 0; mi < 4; mi++)
#pragma unroll
            for (int ni = 0; ni < 2; ni++) {
                wmma::mma_sync(acc[mi][ni], aH[mi], bL[ni], acc[mi][ni]);
                wmma::mma_sync(acc[mi][ni], aL[mi], bH[ni], acc[mi][ni]);
                wmma::mma_sync(acc[mi][ni], aH[mi], bH[ni], acc[mi][ni]);
            }
    }

    CP_WAIT0();
    __syncthreads();              // before Cs aliases pipeline buffers

#pragma unroll
    for (int mi = 0; mi < 4; mi++)
#pragma unroll
        for (int ni = 0; ni < 2; ni++) {
            wmma::store_matrix_sync(&Cs[warp * 256], acc[mi][ni], 16, wmma::mem_row_major);
            __syncwarp();
            int r16 = lane >> 1;
            int c0  = (lane & 1) * 8;
            int row = rowBase + wRow + mi * 16 + r16;
            float v[8];
#pragma unroll
            for (int j = 0; j < 8; j++) v[j] = 0.f;
            int colb = colBase + wCol + ni * 16 + c0;
            if (row < nrows) {
#pragma unroll
                for (int j = 0; j < 8; j++) {
                    v[j] = Cs[warp * 256 + r16 * 16 + c0 + j];
                    if (bias) v[j] += bias[colb + j];
                }
                if (resid) {
                    float4 r0 = *(const float4*)(resid + (size_t)row * ldres + colb);
                    float4 r1 = *(const float4*)(resid + (size_t)row * ldres + colb + 4);
                    float rr[8] = {r0.x, r0.y, r0.z, r0.w, r1.x, r1.y, r1.z, r1.w};
#pragma unroll
                    for (int j = 0; j < 8; j++) {
                        float t = rr[j];
                        if (rscSlot >= 0)
                            t = t * g_aff[rscSlot * 128 + colb + j]
                                  + g_aff[(rscSlot + 1) * 128 + colb + j];
                        v[j] += t;
                    }
                }
                if (doRelu) {
#pragma unroll
                    for (int j = 0; j < 8; j++) v[j] = fmaxf(v[j], 0.f);
                }
                if (C) {
                    *(float4*)(C + (size_t)row * ldc + colb)     = make_float4(v[0], v[1], v[2], v[3]);
                    *(float4*)(C + (size_t)row * ldc + colb + 4) = make_float4(v[4], v[5], v[6], v[7]);
                }
                if (CH) {
                    BF8 h, l;
#pragma unroll
                    for (int j = 0; j < 8; j++) {
                        bf16 hh = __float2bfloat16(v[j]);
                        h.b[j] = hh;
                        l.b[j] = __float2bfloat16(v[j] - __bfloat162float(hh));
                    }
                    *(uint4*)(CH + (size_t)row * ldc + colb) = h.u4;
                    *(uint4*)(CL + (size_t)row * ldc + colb) = l.u4;
                }
            }
            if (statsSlot >= 0) {
#pragma unroll
                for (int j = 0; j < 8; j++) {
                    float sv = v[j];
                    float qv = v[j] * v[j];
#pragma unroll
                    for (int m = 2; m <= 16; m <<= 1) {
                        sv += __shfl_xor_sync(0xffffffffu, sv, m);
                        qv += __shfl_xor_sync(0xffffffffu, qv, m);
                    }
                    if (lane < 2) {
                        int cc = wCol + ni * 16 + (lane ? 8 : 0) + j;
                        atomicAdd(&sSum[cc], sv);
                        atomicAdd(&sSq[cc], qv);
                    }
                }
            }
            __syncwarp();
        }

    if (statsSlot >= 0) {
        __syncthreads();
        if (tid < 128)       atomicAdd(&g_red[statsSlot * 128 + tid], sSum[tid]);
        else if (tid < 256)  atomicAdd(&g_red[(statsSlot + 1) * 128 + tid - 128], sSq[tid - 128]);
    }
}

// --------- merged BN1 finalize + W1 fold/split + b1 fold (one kernel) --------
__global__ void k_fin1w1(const float* __restrict__ W1, const float* __restrict__ b1,
                         const float* __restrict__ gam, const float* __restrict__ bet,
                         int n) {
    __shared__ float sc[128], sh[128];
    int t = threadIdx.x;
    if (t < 128) {
        float mean = g_red[t] / (float)n;
        float var  = g_red[128 + t] / (float)n - mean * mean;
        float inv  = rsqrtf(var + 1e-5f);
        float s    = gam[t] * inv;
        sc[t] = s;
        sh[t] = bet[t] - mean * s;
        if (blockIdx.x == 0) { g_aff[t] = s; g_aff[128 + t] = sh[t]; }
    }
    __syncthreads();
    int i = blockIdx.x * 256 + t;
    int k = i >> 8;
    splitw(sc[k] * W1[i], &g_w1h[i], &g_w1l[i]);
    if (blockIdx.x == 0) {
        float s = b1[t];
        for (int kk = 0; kk < 128; kk++) s += sh[kk] * W1[kk * 256 + t];
        g_b1fold[t] = s;
    }
}

// ------------- merged BN2 finalize + apply (grid-stride float4) --------------
__global__ void k_fin2apply(float* __restrict__ out,
                            const float* __restrict__ gam, const float* __restrict__ bet,
                            int n, int total4) {
    __shared__ float sc[128], sh[128];
    int t = threadIdx.x;
    if (t < 128) {
        float mean = g_red[256 + t] / (float)n;
        float var  = g_red[384 + t] / (float)n - mean * mean;
        float inv  = rsqrtf(var + 1e-5f);
        float s    = gam[t] * inv;
        sc[t] = s;
        sh[t] = bet[t] - mean * s;
    }
    __syncthreads();
    for (int i = blockIdx.x * blockDim.x + t; i < total4; i += gridDim.x * blockDim.x) {
        float4 v = *(float4*)(out + (size_t)i * 4);
        int c = (i * 4) & 127;
        v.x = v.x * sc[c]     + sh[c];
        v.y = v.y * sc[c + 1] + sh[c + 1];
        v.z = v.z * sc[c + 2] + sh[c + 2];
        v.w = v.w * sc[c + 3] + sh[c + 3];
        *(float4*)(out + (size_t)i * 4) = v;
    }
}

// ------------------------------- launcher ------------------------------------
extern "C" void kernel_launch(void* const* d_in, const int* in_sizes, int n_in,
                              void* d_out, int out_size) {
    const float* x   = (const float*)d_in[0];
    const void*  ei  = d_in[1];
    const float* WQ  = (const float*)d_in[2];
    const float* WK  = (const float*)d_in[3];
    const float* WV  = (const float*)d_in[4];
    const float* WO  = (const float*)d_in[5];
    const float* bO  = (const float*)d_in[6];
    const float* W1  = (const float*)d_in[7];
    const float* b1  = (const float*)d_in[8];
    const float* W2  = (const float*)d_in[9];
    const float* b2  = (const float*)d_in[10];
    const float* g1v = (const float*)d_in[11];
    const float* be1 = (const float*)d_in[12];
    const float* g2v = (const float*)d_in[13];
    const float* be2 = (const float*)d_in[14];

    int n = in_sizes[0] / 128;
    int e = in_sizes[1] / 2;
    float* out = (float*)d_out;

    int nb = (n + 1023) / 1024;

    // #1: detect + zero (both streams depend on this)
    k_init<<<(n + 255) / 256, 256>>>(ei, e, n);
    cudaEventRecord(g_e1, 0);

    // main stream: merged x-split + weight-split, then QKV GEMM
    k_prep<<<(n * 32 + 255) / 256, 256>>>(x, n * 32, WQ, WK, WV, WO, W2);

    dim3 gQKV((n + 127) / 128, 3);
    dim3 g1g((n + 127) / 128, 1);
    dim3 g2g((n + 127) / 128, 2);

    pgemm<<<gQKV, 256, SMEM_BYTES>>>(0, 8, 384, 0, 0, -1, n, 128, 384,
                                     0, -1, 0, -1, 0, 0, -1, 0, -1);

    // fork: CSR build on g_s2, overlapping prep/QKV on main
    cudaStreamWaitEvent(g_s2, g_e1, 0);
    k_hist   <<<(e + 255) / 256, 256, 0, g_s2>>>(ei, e);
    k_scan1  <<<nb, 1024, 0, g_s2>>>(n);
    k_scan2  <<<1, 32, 0, g_s2>>>(nb);
    k_scan3  <<<nb, 1024, 0, g_s2>>>(n, e);
    k_scatter<<<(e + 255) / 256, 256, 0, g_s2>>>(ei, e);
    cudaEventRecord(g_e2, g_s2);
    cudaStreamWaitEvent(0, g_e2, 0);

    // join: attention (needs QKV + CSR)
    k_attn<<<(n + 7) / 8, 256>>>(n);

    // h1 = agg @ WO + bO + x  (BN1 stats fused)
    pgemm<<<g1g, 256, SMEM_BYTES>>>(2, 10, 128, 0, 1, 4, n, 128, 128,
                                    bO, -1, x, -1, 1, 128, -1, 0, 0);

    // BN1 finalize + W1 fold/split + b1 fold (one kernel)
    k_fin1w1<<<128, 256>>>(W1, b1, g1v, be1, n);

    // hidden = relu( h1 @ W1' + b1fold )
    pgemm<<<g2g, 256, SMEM_BYTES>>>(4, 12, 256, 0, -1, 6, n, 128, 256,
                                    0, 2, 0, -1, 0, 0, -1, 1, -1);

    // out = hidden @ W2 + b2 + BN1(h1)  (BN2 stats fused)
    pgemm<<<g1g, 256, SMEM_BYTES>>>(6, 14, 128, out, -1, -1, n, 256, 128,
                                    b2, -1, 0, 1, 1, 128, 0, 0, 2);

    // BN2 finalize + apply (one kernel)
    k_fin2apply<<<1600, 256>>>(out, g2v, be2, n, n * 32);
}

// round 13
// speedup vs baseline: 1.0780x; 1.0780x over previous
#include <cuda_runtime.h>
#include <cuda_bf16.h>
#include <cuda_fp16.h>
#include <mma.h>
#include <cstdint>
using namespace nvcuda;

#define NMAX 50000
#define EMAX 500000
#define NPAD (NMAX + 128)

typedef unsigned long long u64;
typedef __nv_bfloat16 bf16;

// ---------------- device scratch (static allocations, allowed) --------------
__device__ float g_buf1[(size_t)NMAX * 128];    // h1 fp32 (residual for FFN2)
__device__ float g_b1fold[256];                 // b1 + sh1^T W1
__device__ float g_qf [(size_t)NMAX * 128];     // Q fp32 (attention)
__device__ __align__(16) __half g_kvh[(size_t)NMAX * 256];  // K|V fp16

__device__ __align__(16) bf16 g_xh  [(size_t)NPAD * 128];
__device__ __align__(16) bf16 g_xl  [(size_t)NPAD * 128];
__device__ __align__(16) bf16 g_aggh[(size_t)NPAD * 128];
__device__ __align__(16) bf16 g_aggl[(size_t)NPAD * 128];
__device__ __align__(16) bf16 g_b1h [(size_t)NPAD * 128];
__device__ __align__(16) bf16 g_b1l [(size_t)NPAD * 128];
__device__ __align__(16) bf16 g_b2h [(size_t)NPAD * 256];
__device__ __align__(16) bf16 g_b2l [(size_t)NPAD * 256];
__device__ __align__(16) bf16 g_wqkvh[128 * 384];
__device__ __align__(16) bf16 g_wqkvl[128 * 384];
__device__ __align__(16) bf16 g_woh [128 * 128];
__device__ __align__(16) bf16 g_wol [128 * 128];
__device__ __align__(16) bf16 g_w1h [128 * 256];
__device__ __align__(16) bf16 g_w1l [128 * 256];
__device__ __align__(16) bf16 g_w2h [256 * 128];
__device__ __align__(16) bf16 g_w2l [256 * 128];

__device__ int   g_cnt   [NMAX];
__device__ int   g_rp    [NMAX + 1];
__device__ int   g_cursor[NMAX];
__device__ int   g_srcs  [EMAX];
__device__ int   g_bsum  [256];
__device__ int   g_is64;
__device__ float g_red[512];
__device__ float g_aff[512];

__device__ __forceinline__ bf16* bfptr(int id) {
    switch (id) {
        case 0:  return g_xh;    case 1:  return g_xl;
        case 2:  return g_aggh;  case 3:  return g_aggl;
        case 4:  return g_b1h;   case 5:  return g_b1l;
        case 6:  return g_b2h;   case 7:  return g_b2l;
        case 8:  return g_wqkvh; case 9:  return g_wqkvl;
        case 10: return g_woh;   case 11: return g_wol;
        case 12: return g_w1h;   case 13: return g_w1l;
        case 14: return g_w2h;   case 15: return g_w2l;
    }
    return 0;
}

__device__ __forceinline__ float* fbptr(int id) {
    switch (id) {
        case 0: return g_qf;
        case 1: return g_buf1;
        case 2: return g_b1fold;
    }
    return 0;
}

__device__ __forceinline__ int edge_at(const void* ei, size_t idx) {
    if (g_is64) return (int)((const long long*)ei)[idx];
    return ((const int*)ei)[idx];
}

union BF4 { bf16 b[4]; u64 uu; };
union BF8 { bf16 b[8]; uint4 u4; };
union HF8 { __half h[8]; uint4 u4; };

__device__ __forceinline__ void cp16(void* smem, const void* gmem) {
    unsigned sa = (unsigned)__cvta_generic_to_shared(smem);
    asm volatile("cp.async.cg.shared.global [%0], [%1], 16;\n" :: "r"(sa), "l"(gmem));
}
#define CP_COMMIT() asm volatile("cp.async.commit_group;\n" ::: "memory")
#define CP_WAIT0()  asm volatile("cp.async.wait_group 0;\n" ::: "memory")

// --------------------- streams/events for fork-join capture ------------------
static cudaStream_t g_s2;
static cudaEvent_t  g_e1, g_e2;
static struct StreamInit {
    StreamInit() {
        cudaStreamCreateWithFlags(&g_s2, cudaStreamNonBlocking);
        cudaEventCreateWithFlags(&g_e1, cudaEventDisableTiming);
        cudaEventCreateWithFlags(&g_e2, cudaEventDisableTiming);
    }
} g_streamInit;

// ---------------------------- small kernels ---------------------------------
__global__ void k_init(const void* ei, int e, int n) {
    int i = blockIdx.x * blockDim.x + threadIdx.x;
    if (blockIdx.x == 0) {
        const long long* p = (const long long*)ei;
        int m = e < 256 ? e : 256;
        int bad = 0;
        if (threadIdx.x < m) {
            long long v = p[threadIdx.x];
            bad = (v < 0 || v >= NMAX);
        }
        int any = __syncthreads_or(bad);
        if (threadIdx.x == 0) g_is64 = !any;
    }
    if (i < n)   g_cnt[i] = 0;
    if (i < 512) g_red[i] = 0.f;
}

__device__ __forceinline__ void splitw(float v, bf16* ph, bf16* pl) {
    bf16 h = __float2bfloat16(v);
    *ph = h;
    *pl = __float2bfloat16(v - __bfloat162float(h));
}

// merged: x hi/lo split + all weight splits (one launch)
__global__ void k_prep(const float* __restrict__ x, int total4,
                       const float* __restrict__ WQ, const float* __restrict__ WK,
                       const float* __restrict__ WV, const float* __restrict__ WO,
                       const float* __restrict__ W2) {
    int i = blockIdx.x * blockDim.x + threadIdx.x;
    if (i < total4) {
        float4 v = *(const float4*)(x + i * 4);
        float vv[4] = {v.x, v.y, v.z, v.w};
        BF4 h, l;
#pragma unroll
        for (int j = 0; j < 4; j++) {
            bf16 hh = __float2bfloat16(vv[j]);
            h.b[j] = hh;
            l.b[j] = __float2bfloat16(vv[j] - __bfloat162float(hh));
        }
        *(u64*)(g_xh + i * 4) = h.uu;
        *(u64*)(g_xl + i * 4) = l.uu;
    }
    if (i < 16384) {
        int k = i >> 7, m = i & 127;
        splitw(WQ[i], &g_wqkvh[k * 384 + m],       &g_wqkvl[k * 384 + m]);
        splitw(WK[i], &g_wqkvh[k * 384 + 128 + m], &g_wqkvl[k * 384 + 128 + m]);
        splitw(WV[i], &g_wqkvh[k * 384 + 256 + m], &g_wqkvl[k * 384 + 256 + m]);
    } else if (i < 32768) {
        int j = i - 16384;
        splitw(WO[j], &g_woh[j], &g_wol[j]);
    } else if (i < 65536) {
        int j = i - 32768;
        splitw(W2[j], &g_w2h[j], &g_w2l[j]);
    }
}

__global__ void k_hist(const void* ei, int e) {
    int i = blockIdx.x * blockDim.x + threadIdx.x;
    if (i < e) atomicAdd(&g_cnt[edge_at(ei, (size_t)e + i)], 1);
}

__global__ void k_scan1(int n) {
    __shared__ int sh[1024];
    int t = threadIdx.x;
    int idx = blockIdx.x * 1024 + t;
    int v = (idx < n) ? g_cnt[idx] : 0;
    sh[t] = v;
    __syncthreads();
    for (int off = 1; off < 1024; off <<= 1) {
        int add = (t >= off) ? sh[t - off] : 0;
        __syncthreads();
        sh[t] += add;
        __syncthreads();
    }
    if (idx < n) g_rp[idx] = sh[t] - v;
    if (t == 1023) g_bsum[blockIdx.x] = sh[1023];
}

__global__ void k_scan2(int nb) {
    if (threadIdx.x == 0) {
        int run = 0;
        for (int i = 0; i < nb; i++) { int c = g_bsum[i]; g_bsum[i] = run; run += c; }
    }
}

__global__ void k_scan3(int n, int e) {
    int idx = blockIdx.x * 1024 + threadIdx.x;
    if (idx < n) {
        int v = g_rp[idx] + g_bsum[blockIdx.x];
        g_rp[idx] = v;
        g_cursor[idx] = v;
    }
    if (idx == 0) g_rp[n] = e;
}

__global__ void k_scatter(const void* ei, int e) {
    int i = blockIdx.x * blockDim.x + threadIdx.x;
    if (i < e) {
        int d = edge_at(ei, (size_t)e + i);
        int s = edge_at(ei, (size_t)i);
        int p = atomicAdd(&g_cursor[d], 1);
        g_srcs[p] = s;
    }
}

// ---------------- attention: one warp per destination node ------------------
// K/V gathered in fp16 (halves L2 traffic); scores/softmax in fp32.
__global__ void k_attn(int n) {
    int warp = (blockIdx.x * blockDim.x + threadIdx.x) >> 5;
    int lane = threadIdx.x & 31;
    if (warp >= n) return;

    float4 q = *(const float4*)(g_qf + (size_t)warp * 128 + lane * 4);

    float ax = 0.f, ay = 0.f, az = 0.f, aw = 0.f, se = 0.f;
    int beg = g_rp[warp], end = g_rp[warp + 1];
    int p = beg;
    for (; p + 1 < end; p += 2) {
        int j0 = g_srcs[p];
        int j1 = g_srcs[p + 1];
        const __half* b0 = g_kvh + (size_t)j0 * 256 + lane * 4;
        const __half* b1 = g_kvh + (size_t)j1 * 256 + lane * 4;
        uint2 k0u = *(const uint2*)b0;
        uint2 v0u = *(const uint2*)(b0 + 128);
        uint2 k1u = *(const uint2*)b1;
        uint2 v1u = *(const uint2*)(b1 + 128);
        float2 k0a = __half22float2(*(__half2*)&k0u.x);
        float2 k0b = __half22float2(*(__half2*)&k0u.y);
        float2 v0a = __half22float2(*(__half2*)&v0u.x);
        float2 v0b = __half22float2(*(__half2*)&v0u.y);
        float2 k1a = __half22float2(*(__half2*)&k1u.x);
        float2 k1b = __half22float2(*(__half2*)&k1u.y);
        float2 v1a = __half22float2(*(__half2*)&v1u.x);
        float2 v1b = __half22float2(*(__half2*)&v1u.y);

        float s0 = q.x * k0a.x + q.y * k0a.y + q.z * k0b.x + q.w * k0b.y;
        float s1 = q.x * k1a.x + q.y * k1a.y + q.z * k1b.x + q.w * k1b.y;
        s0 += __shfl_xor_sync(0xffffffffu, s0, 1);
        s1 += __shfl_xor_sync(0xffffffffu, s1, 1);
        s0 += __shfl_xor_sync(0xffffffffu, s0, 2);
        s1 += __shfl_xor_sync(0xffffffffu, s1, 2);
        s0 = fminf(fmaxf(s0 * 0.25f, -5.f), 5.f);
        s1 = fminf(fmaxf(s1 * 0.25f, -5.f), 5.f);
        float e0 = __expf(s0);
        float e1 = __expf(s1);
        ax += e0 * v0a.x + e1 * v1a.x;
        ay += e0 * v0a.y + e1 * v1a.y;
        az += e0 * v0b.x + e1 * v1b.x;
        aw += e0 * v0b.y + e1 * v1b.y;
        se += e0 + e1;
    }
    if (p < end) {
        int j = g_srcs[p];
        const __half* b0 = g_kvh + (size_t)j * 256 + lane * 4;
        uint2 ku = *(const uint2*)b0;
        uint2 vu = *(const uint2*)(b0 + 128);
        float2 ka = __half22float2(*(__half2*)&ku.x);
        float2 kb = __half22float2(*(__half2*)&ku.y);
        float2 va = __half22float2(*(__half2*)&vu.x);
        float2 vb = __half22float2(*(__half2*)&vu.y);
        float s = q.x * ka.x + q.y * ka.y + q.z * kb.x + q.w * kb.y;
        s += __shfl_xor_sync(0xffffffffu, s, 1);
        s += __shfl_xor_sync(0xffffffffu, s, 2);
        s = fminf(fmaxf(s * 0.25f, -5.f), 5.f);
        float e = __expf(s);
        ax += e * va.x; ay += e * va.y; az += e * vb.x; aw += e * vb.y;
        se += e;
    }
    float inv = 1.0f / (se + 1e-16f);
    float o[4] = {ax * inv, ay * inv, az * inv, aw * inv};
    BF4 oh, ol;
#pragma unroll
    for (int j = 0; j < 4; j++) {
        bf16 h = __float2bfloat16(o[j]);
        oh.b[j] = h;
        ol.b[j] = __float2bfloat16(o[j] - __bfloat162float(h));
    }
    *(u64*)(g_aggh + (size_t)warp * 128 + lane * 4) = oh.uu;
    *(u64*)(g_aggl + (size_t)warp * 128 + lane * 4) = ol.uu;
}

// ------ tensor-core GEMM: bf16 3-term split, cp.async double-buffered -------
struct PipeBufs {
    unsigned short AsH[2][128][24];
    unsigned short AsL[2][128][24];
    unsigned short WsH[2][16][136];
    unsigned short WsL[2][16][136];
};
union SmemU {
    PipeBufs p;
    float Cs[8][16][16];
};

__global__ __launch_bounds__(256) void pgemm(
    int AHid, int WHid, int Wld,
    float* Cext, int Cid, int CHid,
    int nrows, int K, int ldc,
    const float* biasExt, int biasId,
    const float* Rext, int rid, int hasResid, int ldres, int rscSlot,
    int doRelu, int statsSlot, int qkvMode)
{
    __shared__ __align__(16) SmemU sm;
    __shared__ float sSum[128], sSq[128];

    const bf16* AH = bfptr(AHid);
    const bf16* AL = bfptr(AHid + 1);
    const bf16* WH = bfptr(WHid);
    const bf16* WL = bfptr(WHid + 1);
    float* C = (Cid >= 0) ? fbptr(Cid) : Cext;
    bf16* CH = (CHid >= 0) ? bfptr(CHid) : 0;
    bf16* CL = (CHid >= 0) ? bfptr(CHid + 1) : 0;
    const float* bias = (biasId >= 0) ? fbptr(biasId) : biasExt;
    const float* resid = hasResid ? ((rid >= 0) ? fbptr(rid) : Rext) : 0;

    int tid  = threadIdx.x;
    int warp = tid >> 5;
    int lane = tid & 31;
    int rowBase = blockIdx.x * 128;
    int colBase = blockIdx.y * 128;

    int wRow = (warp >> 2) * 64;
    int wCol = (warp & 3) * 32;

    if (statsSlot >= 0 && tid < 128) { sSum[tid] = 0.f; sSq[tid] = 0.f; }

    int ar = tid >> 1;
    int ak = (tid & 1) * 8;
    int wr = tid >> 4;
    int wc = (tid & 15) * 8;

    wmma::fragment<wmma::accumulator, 16, 16, 16, float> acc[4][2];
#pragma unroll
    for (int i = 0; i < 4; i++)
#pragma unroll
        for (int j = 0; j < 2; j++) wmma::fill_fragment(acc[i][j], 0.f);

    const size_t aOff = (size_t)(rowBase + ar) * K + ak;

    cp16(&sm.p.AsH[0][ar][ak], AH + aOff);
    cp16(&sm.p.AsL[0][ar][ak], AL + aOff);
    cp16(&sm.p.WsH[0][wr][wc], WH + (size_t)wr * Wld + colBase + wc);
    cp16(&sm.p.WsL[0][wr][wc], WL + (size_t)wr * Wld + colBase + wc);
    CP_COMMIT();

    int nIter = K >> 4;
    for (int it = 0; it < nIter; it++) {
        int st = it & 1;
        CP_WAIT0();
        __syncthreads();

        int kn = (it + 1) << 4;
        if (kn < K) {
            int sn = st ^ 1;
            cp16(&sm.p.AsH[sn][ar][ak], AH + aOff + kn);
            cp16(&sm.p.AsL[sn][ar][ak], AL + aOff + kn);
            cp16(&sm.p.WsH[sn][wr][wc], WH + (size_t)(kn + wr) * Wld + colBase + wc);
            cp16(&sm.p.WsL[sn][wr][wc], WL + (size_t)(kn + wr) * Wld + colBase + wc);
            CP_COMMIT();
        }

        wmma::fragment<wmma::matrix_a, 16, 16, 16, bf16, wmma::row_major> aH[4], aL[4];
        wmma::fragment<wmma::matrix_b, 16, 16, 16, bf16, wmma::row_major> bH[2], bL[2];
#pragma unroll
        for (int mi = 0; mi < 4; mi++) {
            wmma::load_matrix_sync(aH[mi], (const bf16*)&sm.p.AsH[st][wRow + mi * 16][0], 24);
            wmma::load_matrix_sync(aL[mi], (const bf16*)&sm.p.AsL[st][wRow + mi * 16][0], 24);
        }
#pragma unroll
        for (int ni = 0; ni < 2; ni++) {
            wmma::load_matrix_sync(bH[ni], (const bf16*)&sm.p.WsH[st][0][wCol + ni * 16], 136);
            wmma::load_matrix_sync(bL[ni], (const bf16*)&sm.p.WsL[st][0][wCol + ni * 16], 136);
        }
#pragma unroll
        for (int mi = 0; mi < 4; mi++)
#pragma unroll
            for (int ni = 0; ni < 2; ni++) {
                wmma::mma_sync(acc[mi][ni], aH[mi], bL[ni], acc[mi][ni]);
                wmma::mma_sync(acc[mi][ni], aL[mi], bH[ni], acc[mi][ni]);
                wmma::mma_sync(acc[mi][ni], aH[mi], bH[ni], acc[mi][ni]);
            }
    }

    __syncthreads();   // before Cs aliases pipeline buffers

#pragma unroll
    for (int mi = 0; mi < 4; mi++)
#pragma unroll
        for (int ni = 0; ni < 2; ni++) {
            wmma::store_matrix_sync(&sm.Cs[warp][0][0], acc[mi][ni], 16, wmma::mem_row_major);
            __syncwarp();
            int r16 = lane >> 1;
            int c0  = (lane & 1) * 8;
            int row = rowBase + wRow + mi * 16 + r16;
            float v[8];
#pragma unroll
            for (int j = 0; j < 8; j++) v[j] = 0.f;
            int colb = colBase + wCol + ni * 16 + c0;
            if (row < nrows) {
#pragma unroll
                for (int j = 0; j < 8; j++) {
                    v[j] = sm.Cs[warp][r16][c0 + j];
                    if (bias) v[j] += bias[colb + j];
                }
                if (resid) {
                    float4 r0 = *(const float4*)(resid + (size_t)row * ldres + colb);
                    float4 r1 = *(const float4*)(resid + (size_t)row * ldres + colb + 4);
                    float rr[8] = {r0.x, r0.y, r0.z, r0.w, r1.x, r1.y, r1.z, r1.w};
#pragma unroll
                    for (int j = 0; j < 8; j++) {
                        float t = rr[j];
                        if (rscSlot >= 0)
                            t = t * g_aff[rscSlot * 128 + colb + j]
                                  + g_aff[(rscSlot + 1) * 128 + colb + j];
                        v[j] += t;
                    }
                }
                if (doRelu) {
#pragma unroll
                    for (int j = 0; j < 8; j++) v[j] = fmaxf(v[j], 0.f);
                }
                if (qkvMode) {
                    if (colBase == 0) {               // Q -> fp32
                        float* cp = g_qf + (size_t)row * 128 + colb;
                        *(float4*)cp       = make_float4(v[0], v[1], v[2], v[3]);
                        *(float4*)(cp + 4) = make_float4(v[4], v[5], v[6], v[7]);
                    } else {                           // K|V -> fp16
                        HF8 hf;
#pragma unroll
                        for (int j = 0; j < 8; j++) hf.h[j] = __float2half_rn(v[j]);
                        *(uint4*)(g_kvh + (size_t)row * 256 + (colb - 128)) = hf.u4;
                    }
                } else {
                    if (C) {
                        *(float4*)(C + (size_t)row * ldc + colb)     = make_float4(v[0], v[1], v[2], v[3]);
                        *(float4*)(C + (size_t)row * ldc + colb + 4) = make_float4(v[4], v[5], v[6], v[7]);
                    }
                    if (CH) {
                        BF8 h, l;
#pragma unroll
                        for (int j = 0; j < 8; j++) {
                            bf16 hh = __float2bfloat16(v[j]);
                            h.b[j] = hh;
                            l.b[j] = __float2bfloat16(v[j] - __bfloat162float(hh));
                        }
                        *(uint4*)(CH + (size_t)row * ldc + colb) = h.u4;
                        *(uint4*)(CL + (size_t)row * ldc + colb) = l.u4;
                    }
                }
            }
            if (statsSlot >= 0) {
#pragma unroll
                for (int j = 0; j < 8; j++) {
                    float sv = v[j];
                    float qv = v[j] * v[j];
#pragma unroll
                    for (int m = 2; m <= 16; m <<= 1) {
                        sv += __shfl_xor_sync(0xffffffffu, sv, m);
                        qv += __shfl_xor_sync(0xffffffffu, qv, m);
                    }
                    if (lane < 2) {
                        int cc = wCol + ni * 16 + (lane ? 8 : 0) + j;
                        atomicAdd(&sSum[cc], sv);
                        atomicAdd(&sSq[cc], qv);
                    }
                }
            }
            __syncwarp();
        }

    if (statsSlot >= 0) {
        __syncthreads();
        if (tid < 128)       atomicAdd(&g_red[statsSlot * 128 + tid], sSum[tid]);
        else if (tid < 256)  atomicAdd(&g_red[(statsSlot + 1) * 128 + tid - 128], sSq[tid - 128]);
    }
}

// --------- merged BN1 finalize + W1 fold/split + b1 fold (one kernel) --------
__global__ void k_fin1w1(const float* __restrict__ W1, const float* __restrict__ b1,
                         const float* __restrict__ gam, const float* __restrict__ bet,
                         int n) {
    __shared__ float sc[128], sh[128];
    int t = threadIdx.x;
    if (t < 128) {
        float mean = g_red[t] / (float)n;
        float var  = g_red[128 + t] / (float)n - mean * mean;
        float inv  = rsqrtf(var + 1e-5f);
        float s    = gam[t] * inv;
        sc[t] = s;
        sh[t] = bet[t] - mean * s;
        if (blockIdx.x == 0) { g_aff[t] = s; g_aff[128 + t] = sh[t]; }
    }
    __syncthreads();
    int i = blockIdx.x * 256 + t;
    int k = i >> 8;
    splitw(sc[k] * W1[i], &g_w1h[i], &g_w1l[i]);
    if (blockIdx.x == 0) {
        float s = b1[t];
        for (int kk = 0; kk < 128; kk++) s += sh[kk] * W1[kk * 256 + t];
        g_b1fold[t] = s;
    }
}

// ------------- merged BN2 finalize + apply (grid-stride float4) --------------
__global__ void k_fin2apply(float* __restrict__ out,
                            const float* __restrict__ gam, const float* __restrict__ bet,
                            int n, int total4) {
    __shared__ float sc[128], sh[128];
    int t = threadIdx.x;
    if (t < 128) {
        float mean = g_red[256 + t] / (float)n;
        float var  = g_red[384 + t] / (float)n - mean * mean;
        float inv  = rsqrtf(var + 1e-5f);
        float s    = gam[t] * inv;
        sc[t] = s;
        sh[t] = bet[t] - mean * s;
    }
    __syncthreads();
    for (int i = blockIdx.x * blockDim.x + t; i < total4; i += gridDim.x * blockDim.x) {
        float4 v = *(float4*)(out + (size_t)i * 4);
        int c = (i * 4) & 127;
        v.x = v.x * sc[c]     + sh[c];
        v.y = v.y * sc[c + 1] + sh[c + 1];
        v.z = v.z * sc[c + 2] + sh[c + 2];
        v.w = v.w * sc[c + 3] + sh[c + 3];
        *(float4*)(out + (size_t)i * 4) = v;
    }
}

// ------------------------------- launcher ------------------------------------
extern "C" void kernel_launch(void* const* d_in, const int* in_sizes, int n_in,
                              void* d_out, int out_size) {
    const float* x   = (const float*)d_in[0];
    const void*  ei  = d_in[1];
    const float* WQ  = (const float*)d_in[2];
    const float* WK  = (const float*)d_in[3];
    const float* WV  = (const float*)d_in[4];
    const float* WO  = (const float*)d_in[5];
    const float* bO  = (const float*)d_in[6];
    const float* W1  = (const float*)d_in[7];
    const float* b1  = (const float*)d_in[8];
    const float* W2  = (const float*)d_in[9];
    const float* b2  = (const float*)d_in[10];
    const float* g1v = (const float*)d_in[11];
    const float* be1 = (const float*)d_in[12];
    const float* g2v = (const float*)d_in[13];
    const float* be2 = (const float*)d_in[14];

    int n = in_sizes[0] / 128;
    int e = in_sizes[1] / 2;
    float* out = (float*)d_out;

    int nb = (n + 1023) / 1024;

    // #1: detect + zero (both streams depend on this)
    k_init<<<(n + 255) / 256, 256>>>(ei, e, n);
    cudaEventRecord(g_e1, 0);

    // main stream: merged x-split + weight-split, then QKV GEMM
    k_prep<<<(n * 32 + 255) / 256, 256>>>(x, n * 32, WQ, WK, WV, WO, W2);

    dim3 gQKV((n + 127) / 128, 3);
    dim3 g1g((n + 127) / 128, 1);
    dim3 g2g((n + 127) / 128, 2);

    // QKV: x @ [WQ|WK|WV] -> Q fp32 (g_qf) + K|V fp16 (g_kvh)
    pgemm<<<gQKV, 256>>>(0, 8, 384, 0, -1, -1, n, 128, 384,
                         0, -1, 0, -1, 0, 0, -1, 0, -1, 1);

    // fork: CSR build on g_s2, overlapping prep/QKV on main
    cudaStreamWaitEvent(g_s2, g_e1, 0);
    k_hist   <<<(e + 255) / 256, 256, 0, g_s2>>>(ei, e);
    k_scan1  <<<nb, 1024, 0, g_s2>>>(n);
    k_scan2  <<<1, 32, 0, g_s2>>>(nb);
    k_scan3  <<<nb, 1024, 0, g_s2>>>(n, e);
    k_scatter<<<(e + 255) / 256, 256, 0, g_s2>>>(ei, e);
    cudaEventRecord(g_e2, g_s2);
    cudaStreamWaitEvent(0, g_e2, 0);

    // join: attention (needs QKV + CSR)
    k_attn<<<(n + 7) / 8, 256>>>(n);

    // h1 = agg @ WO + bO + x  (BN1 stats fused)
    pgemm<<<g1g, 256>>>(2, 10, 128, 0, 1, 4, n, 128, 128,
                        bO, -1, x, -1, 1, 128, -1, 0, 0, 0);

    // BN1 finalize + W1 fold/split + b1 fold (one kernel)
    k_fin1w1<<<128, 256>>>(W1, b1, g1v, be1, n);

    // hidden = relu( h1 @ W1' + b1fold )
    pgemm<<<g2g, 256>>>(4, 12, 256, 0, -1, 6, n, 128, 256,
                        0, 2, 0, -1, 0, 0, -1, 1, -1, 0);

    // out = hidden @ W2 + b2 + BN1(h1)  (BN2 stats fused)
    pgemm<<<g1g, 256>>>(6, 14, 128, out, -1, -1, n, 256, 128,
                        b2, -1, 0, 1, 1, 128, 0, 0, 2, 0);

    // BN2 finalize + apply (one kernel)
    k_fin2apply<<<1600, 256>>>(out, g2v, be2, n, n * 32);
}

// round 14
// speedup vs baseline: 1.0929x; 1.0138x over previous
#include <cuda_runtime.h>
#include <cuda_bf16.h>
#include <cuda_fp16.h>
#include <mma.h>
#include <cstdint>
using namespace nvcuda;

#define NMAX 50000
#define EMAX 500000
#define NPAD (NMAX + 128)

typedef unsigned long long u64;
typedef __nv_bfloat16 bf16;

// ---------------- device scratch (static allocations, allowed) --------------
__device__ float g_buf1[(size_t)NMAX * 128];    // h1 fp32 (residual for FFN2)
__device__ float g_b1fold[256];                 // b1 + sh1^T W1
__device__ float g_qf [(size_t)NMAX * 128];     // Q fp32 (attention)
__device__ __align__(16) __half g_kvh[(size_t)NMAX * 256];  // K|V fp16

__device__ __align__(16) bf16 g_xh  [(size_t)NPAD * 128];
__device__ __align__(16) bf16 g_xl  [(size_t)NPAD * 128];
__device__ __align__(16) bf16 g_aggh[(size_t)NPAD * 128];
__device__ __align__(16) bf16 g_aggl[(size_t)NPAD * 128];
__device__ __align__(16) bf16 g_b1h [(size_t)NPAD * 128];
__device__ __align__(16) bf16 g_b1l [(size_t)NPAD * 128];
__device__ __align__(16) bf16 g_b2h [(size_t)NPAD * 256];
__device__ __align__(16) bf16 g_b2l [(size_t)NPAD * 256];
__device__ __align__(16) bf16 g_wqkvh[128 * 384];
__device__ __align__(16) bf16 g_wqkvl[128 * 384];
__device__ __align__(16) bf16 g_woh [128 * 128];
__device__ __align__(16) bf16 g_wol [128 * 128];
__device__ __align__(16) bf16 g_w1h [128 * 256];
__device__ __align__(16) bf16 g_w1l [128 * 256];
__device__ __align__(16) bf16 g_w2h [256 * 128];
__device__ __align__(16) bf16 g_w2l [256 * 128];

__device__ int   g_cnt   [NMAX];
__device__ int   g_rp    [NMAX + 1];
__device__ int   g_cursor[NMAX];
__device__ int   g_srcs  [EMAX];
__device__ int   g_bsum  [256];
__device__ int   g_is64;
__device__ float g_red[512];
__device__ float g_aff[512];

__device__ __forceinline__ bf16* bfptr(int id) {
    switch (id) {
        case 0:  return g_xh;    case 1:  return g_xl;
        case 2:  return g_aggh;  case 3:  return g_aggl;
        case 4:  return g_b1h;   case 5:  return g_b1l;
        case 6:  return g_b2h;   case 7:  return g_b2l;
        case 8:  return g_wqkvh; case 9:  return g_wqkvl;
        case 10: return g_woh;   case 11: return g_wol;
        case 12: return g_w1h;   case 13: return g_w1l;
        case 14: return g_w2h;   case 15: return g_w2l;
    }
    return 0;
}

__device__ __forceinline__ float* fbptr(int id) {
    switch (id) {
        case 0: return g_qf;
        case 1: return g_buf1;
        case 2: return g_b1fold;
    }
    return 0;
}

__device__ __forceinline__ int edge_at(const void* ei, size_t idx) {
    if (g_is64) return (int)((const long long*)ei)[idx];
    return ((const int*)ei)[idx];
}

union BF4 { bf16 b[4]; u64 uu; };
union BF8 { bf16 b[8]; uint4 u4; };
union HF8 { __half h[8]; uint4 u4; };

__device__ __forceinline__ void cp16(void* smem, const void* gmem) {
    unsigned sa = (unsigned)__cvta_generic_to_shared(smem);
    asm volatile("cp.async.cg.shared.global [%0], [%1], 16;\n" :: "r"(sa), "l"(gmem));
}
#define CP_COMMIT() asm volatile("cp.async.commit_group;\n" ::: "memory")
#define CP_WAIT0()  asm volatile("cp.async.wait_group 0;\n" ::: "memory")

// --------------------- streams/events for fork-join capture ------------------
static cudaStream_t g_s2;
static cudaEvent_t  g_e1, g_e2;
static struct StreamInit {
    StreamInit() {
        cudaStreamCreateWithFlags(&g_s2, cudaStreamNonBlocking);
        cudaEventCreateWithFlags(&g_e1, cudaEventDisableTiming);
        cudaEventCreateWithFlags(&g_e2, cudaEventDisableTiming);
    }
} g_streamInit;

// ---------------------------- small kernels ---------------------------------
__global__ void k_init(const void* ei, int e, int n) {
    int i = blockIdx.x * blockDim.x + threadIdx.x;
    if (blockIdx.x == 0) {
        const long long* p = (const long long*)ei;
        int m = e < 256 ? e : 256;
        int bad = 0;
        if (threadIdx.x < m) {
            long long v = p[threadIdx.x];
            bad = (v < 0 || v >= NMAX);
        }
        int any = __syncthreads_or(bad);
        if (threadIdx.x == 0) g_is64 = !any;
    }
    if (i < n)   g_cnt[i] = 0;
    if (i < 512) g_red[i] = 0.f;
}

__device__ __forceinline__ void splitw(float v, bf16* ph, bf16* pl) {
    bf16 h = __float2bfloat16(v);
    *ph = h;
    *pl = __float2bfloat16(v - __bfloat162float(h));
}

// merged: x hi/lo split + all weight splits (one launch)
__global__ void k_prep(const float* __restrict__ x, int total4,
                       const float* __restrict__ WQ, const float* __restrict__ WK,
                       const float* __restrict__ WV, const float* __restrict__ WO,
                       const float* __restrict__ W2) {
    int i = blockIdx.x * blockDim.x + threadIdx.x;
    if (i < total4) {
        float4 v = *(const float4*)(x + i * 4);
        float vv[4] = {v.x, v.y, v.z, v.w};
        BF4 h, l;
#pragma unroll
        for (int j = 0; j < 4; j++) {
            bf16 hh = __float2bfloat16(vv[j]);
            h.b[j] = hh;
            l.b[j] = __float2bfloat16(vv[j] - __bfloat162float(hh));
        }
        *(u64*)(g_xh + i * 4) = h.uu;
        *(u64*)(g_xl + i * 4) = l.uu;
    }
    if (i < 16384) {
        int k = i >> 7, m = i & 127;
        splitw(WQ[i], &g_wqkvh[k * 384 + m],       &g_wqkvl[k * 384 + m]);
        splitw(WK[i], &g_wqkvh[k * 384 + 128 + m], &g_wqkvl[k * 384 + 128 + m]);
        splitw(WV[i], &g_wqkvh[k * 384 + 256 + m], &g_wqkvl[k * 384 + 256 + m]);
    } else if (i < 32768) {
        int j = i - 16384;
        splitw(WO[j], &g_woh[j], &g_wol[j]);
    } else if (i < 65536) {
        int j = i - 32768;
        splitw(W2[j], &g_w2h[j], &g_w2l[j]);
    }
}

__global__ void k_hist(const void* ei, int e) {
    int i = blockIdx.x * blockDim.x + threadIdx.x;
    if (i < e) atomicAdd(&g_cnt[edge_at(ei, (size_t)e + i)], 1);
}

__global__ void k_scan1(int n) {
    __shared__ int sh[1024];
    int t = threadIdx.x;
    int idx = blockIdx.x * 1024 + t;
    int v = (idx < n) ? g_cnt[idx] : 0;
    sh[t] = v;
    __syncthreads();
    for (int off = 1; off < 1024; off <<= 1) {
        int add = (t >= off) ? sh[t - off] : 0;
        __syncthreads();
        sh[t] += add;
        __syncthreads();
    }
    if (idx < n) g_rp[idx] = sh[t] - v;
    if (t == 1023) g_bsum[blockIdx.x] = sh[1023];
}

__global__ void k_scan2(int nb) {
    if (threadIdx.x == 0) {
        int run = 0;
        for (int i = 0; i < nb; i++) { int c = g_bsum[i]; g_bsum[i] = run; run += c; }
    }
}

__global__ void k_scan3(int n, int e) {
    int idx = blockIdx.x * 1024 + threadIdx.x;
    if (idx < n) {
        int v = g_rp[idx] + g_bsum[blockIdx.x];
        g_rp[idx] = v;
        g_cursor[idx] = v;
    }
    if (idx == 0) g_rp[n] = e;
}

__global__ void k_scatter(const void* ei, int e) {
    int i = blockIdx.x * blockDim.x + threadIdx.x;
    if (i < e) {
        int d = edge_at(ei, (size_t)e + i);
        int s = edge_at(ei, (size_t)i);
        int p = atomicAdd(&g_cursor[d], 1);
        g_srcs[p] = s;
    }
}

// ---------------- attention: one warp per destination node ------------------
// K/V gathered in fp16 (halves L2 traffic); scores/softmax in fp32.
__global__ void k_attn(int n) {
    int warp = (blockIdx.x * blockDim.x + threadIdx.x) >> 5;
    int lane = threadIdx.x & 31;
    if (warp >= n) return;

    float4 q = *(const float4*)(g_qf + (size_t)warp * 128 + lane * 4);

    float ax = 0.f, ay = 0.f, az = 0.f, aw = 0.f, se = 0.f;
    int beg = g_rp[warp], end = g_rp[warp + 1];
    int p = beg;
    for (; p + 1 < end; p += 2) {
        int j0 = g_srcs[p];
        int j1 = g_srcs[p + 1];
        const __half* b0 = g_kvh + (size_t)j0 * 256 + lane * 4;
        const __half* b1 = g_kvh + (size_t)j1 * 256 + lane * 4;
        uint2 k0u = *(const uint2*)b0;
        uint2 v0u = *(const uint2*)(b0 + 128);
        uint2 k1u = *(const uint2*)b1;
        uint2 v1u = *(const uint2*)(b1 + 128);
        float2 k0a = __half22float2(*(__half2*)&k0u.x);
        float2 k0b = __half22float2(*(__half2*)&k0u.y);
        float2 v0a = __half22float2(*(__half2*)&v0u.x);
        float2 v0b = __half22float2(*(__half2*)&v0u.y);
        float2 k1a = __half22float2(*(__half2*)&k1u.x);
        float2 k1b = __half22float2(*(__half2*)&k1u.y);
        float2 v1a = __half22float2(*(__half2*)&v1u.x);
        float2 v1b = __half22float2(*(__half2*)&v1u.y);

        float s0 = q.x * k0a.x + q.y * k0a.y + q.z * k0b.x + q.w * k0b.y;
        float s1 = q.x * k1a.x + q.y * k1a.y + q.z * k1b.x + q.w * k1b.y;
        s0 += __shfl_xor_sync(0xffffffffu, s0, 1);
        s1 += __shfl_xor_sync(0xffffffffu, s1, 1);
        s0 += __shfl_xor_sync(0xffffffffu, s0, 2);
        s1 += __shfl_xor_sync(0xffffffffu, s1, 2);
        s0 = fminf(fmaxf(s0 * 0.25f, -5.f), 5.f);
        s1 = fminf(fmaxf(s1 * 0.25f, -5.f), 5.f);
        float e0 = __expf(s0);
        float e1 = __expf(s1);
        ax += e0 * v0a.x + e1 * v1a.x;
        ay += e0 * v0a.y + e1 * v1a.y;
        az += e0 * v0b.x + e1 * v1b.x;
        aw += e0 * v0b.y + e1 * v1b.y;
        se += e0 + e1;
    }
    if (p < end) {
        int j = g_srcs[p];
        const __half* b0 = g_kvh + (size_t)j * 256 + lane * 4;
        uint2 ku = *(const uint2*)b0;
        uint2 vu = *(const uint2*)(b0 + 128);
        float2 ka = __half22float2(*(__half2*)&ku.x);
        float2 kb = __half22float2(*(__half2*)&ku.y);
        float2 va = __half22float2(*(__half2*)&vu.x);
        float2 vb = __half22float2(*(__half2*)&vu.y);
        float s = q.x * ka.x + q.y * ka.y + q.z * kb.x + q.w * kb.y;
        s += __shfl_xor_sync(0xffffffffu, s, 1);
        s += __shfl_xor_sync(0xffffffffu, s, 2);
        s = fminf(fmaxf(s * 0.25f, -5.f), 5.f);
        float e = __expf(s);
        ax += e * va.x; ay += e * va.y; az += e * vb.x; aw += e * vb.y;
        se += e;
    }
    float inv = 1.0f / (se + 1e-16f);
    float o[4] = {ax * inv, ay * inv, az * inv, aw * inv};
    BF4 oh, ol;
#pragma unroll
    for (int j = 0; j < 4; j++) {
        bf16 h = __float2bfloat16(o[j]);
        oh.b[j] = h;
        ol.b[j] = __float2bfloat16(o[j] - __bfloat162float(h));
    }
    *(u64*)(g_aggh + (size_t)warp * 128 + lane * 4) = oh.uu;
    *(u64*)(g_aggl + (size_t)warp * 128 + lane * 4) = ol.uu;
}

// ------ tensor-core GEMM: bf16 split, cp.async double-buffered --------------
// terms==3: aH*bL + aL*bH + aH*bH (fp32-grade). terms==2: aL*bH + aH*bH
// (drops weight-lo cross term; used for QKV whose error dilutes ~20x through
// the softmax path).
struct PipeBufs {
    unsigned short AsH[2][128][24];
    unsigned short AsL[2][128][24];
    unsigned short WsH[2][16][136];
    unsigned short WsL[2][16][136];
};
union SmemU {
    PipeBufs p;
    float Cs[8][16][16];
};

__global__ __launch_bounds__(256) void pgemm(
    int AHid, int WHid, int Wld,
    float* Cext, int Cid, int CHid,
    int nrows, int K, int ldc,
    const float* biasExt, int biasId,
    const float* Rext, int rid, int hasResid, int ldres, int rscSlot,
    int doRelu, int statsSlot, int qkvMode, int terms)
{
    __shared__ __align__(16) SmemU sm;
    __shared__ float sSum[128], sSq[128];

    const bf16* AH = bfptr(AHid);
    const bf16* AL = bfptr(AHid + 1);
    const bf16* WH = bfptr(WHid);
    const bf16* WL = bfptr(WHid + 1);
    float* C = (Cid >= 0) ? fbptr(Cid) : Cext;
    bf16* CH = (CHid >= 0) ? bfptr(CHid) : 0;
    bf16* CL = (CHid >= 0) ? bfptr(CHid + 1) : 0;
    const float* bias = (biasId >= 0) ? fbptr(biasId) : biasExt;
    const float* resid = hasResid ? ((rid >= 0) ? fbptr(rid) : Rext) : 0;

    int tid  = threadIdx.x;
    int warp = tid >> 5;
    int lane = tid & 31;
    int rowBase = blockIdx.x * 128;
    int colBase = blockIdx.y * 128;

    int wRow = (warp >> 2) * 64;
    int wCol = (warp & 3) * 32;

    if (statsSlot >= 0 && tid < 128) { sSum[tid] = 0.f; sSq[tid] = 0.f; }

    int ar = tid >> 1;
    int ak = (tid & 1) * 8;
    int wr = tid >> 4;
    int wc = (tid & 15) * 8;

    wmma::fragment<wmma::accumulator, 16, 16, 16, float> acc[4][2];
#pragma unroll
    for (int i = 0; i < 4; i++)
#pragma unroll
        for (int j = 0; j < 2; j++) wmma::fill_fragment(acc[i][j], 0.f);

    const size_t aOff = (size_t)(rowBase + ar) * K + ak;

    cp16(&sm.p.AsH[0][ar][ak], AH + aOff);
    cp16(&sm.p.AsL[0][ar][ak], AL + aOff);
    cp16(&sm.p.WsH[0][wr][wc], WH + (size_t)wr * Wld + colBase + wc);
    if (terms == 3) cp16(&sm.p.WsL[0][wr][wc], WL + (size_t)wr * Wld + colBase + wc);
    CP_COMMIT();

    int nIter = K >> 4;
    for (int it = 0; it < nIter; it++) {
        int st = it & 1;
        CP_WAIT0();
        __syncthreads();

        int kn = (it + 1) << 4;
        if (kn < K) {
            int sn = st ^ 1;
            cp16(&sm.p.AsH[sn][ar][ak], AH + aOff + kn);
            cp16(&sm.p.AsL[sn][ar][ak], AL + aOff + kn);
            cp16(&sm.p.WsH[sn][wr][wc], WH + (size_t)(kn + wr) * Wld + colBase + wc);
            if (terms == 3) cp16(&sm.p.WsL[sn][wr][wc], WL + (size_t)(kn + wr) * Wld + colBase + wc);
            CP_COMMIT();
        }

        wmma::fragment<wmma::matrix_a, 16, 16, 16, bf16, wmma::row_major> aH[4], aL[4];
        wmma::fragment<wmma::matrix_b, 16, 16, 16, bf16, wmma::row_major> bH[2], bL[2];
#pragma unroll
        for (int mi = 0; mi < 4; mi++) {
            wmma::load_matrix_sync(aH[mi], (const bf16*)&sm.p.AsH[st][wRow + mi * 16][0], 24);
            wmma::load_matrix_sync(aL[mi], (const bf16*)&sm.p.AsL[st][wRow + mi * 16][0], 24);
        }
#pragma unroll
        for (int ni = 0; ni < 2; ni++) {
            wmma::load_matrix_sync(bH[ni], (const bf16*)&sm.p.WsH[st][0][wCol + ni * 16], 136);
            if (terms == 3)
                wmma::load_matrix_sync(bL[ni], (const bf16*)&sm.p.WsL[st][0][wCol + ni * 16], 136);
        }
#pragma unroll
        for (int mi = 0; mi < 4; mi++)
#pragma unroll
            for (int ni = 0; ni < 2; ni++) {
                if (terms == 3)
                    wmma::mma_sync(acc[mi][ni], aH[mi], bL[ni], acc[mi][ni]);
                wmma::mma_sync(acc[mi][ni], aL[mi], bH[ni], acc[mi][ni]);
                wmma::mma_sync(acc[mi][ni], aH[mi], bH[ni], acc[mi][ni]);
            }
    }

    __syncthreads();   // before Cs aliases pipeline buffers

#pragma unroll
    for (int mi = 0; mi < 4; mi++)
#pragma unroll
        for (int ni = 0; ni < 2; ni++) {
            wmma::store_matrix_sync(&sm.Cs[warp][0][0], acc[mi][ni], 16, wmma::mem_row_major);
            __syncwarp();
            int r16 = lane >> 1;
            int c0  = (lane & 1) * 8;
            int row = rowBase + wRow + mi * 16 + r16;
            float v[8];
#pragma unroll
            for (int j = 0; j < 8; j++) v[j] = 0.f;
            int colb = colBase + wCol + ni * 16 + c0;
            if (row < nrows) {
#pragma unroll
                for (int j = 0; j < 8; j++) {
                    v[j] = sm.Cs[warp][r16][c0 + j];
                    if (bias) v[j] += bias[colb + j];
                }
                if (resid) {
                    float4 r0 = *(const float4*)(resid + (size_t)row * ldres + colb);
                    float4 r1 = *(const float4*)(resid + (size_t)row * ldres + colb + 4);
                    float rr[8] = {r0.x, r0.y, r0.z, r0.w, r1.x, r1.y, r1.z, r1.w};
#pragma unroll
                    for (int j = 0; j < 8; j++) {
                        float t = rr[j];
                        if (rscSlot >= 0)
                            t = t * g_aff[rscSlot * 128 + colb + j]
                                  + g_aff[(rscSlot + 1) * 128 + colb + j];
                        v[j] += t;
                    }
                }
                if (doRelu) {
#pragma unroll
                    for (int j = 0; j < 8; j++) v[j] = fmaxf(v[j], 0.f);
                }
                if (qkvMode) {
                    if (colBase == 0) {               // Q -> fp32
                        float* cp = g_qf + (size_t)row * 128 + colb;
                        *(float4*)cp       = make_float4(v[0], v[1], v[2], v[3]);
                        *(float4*)(cp + 4) = make_float4(v[4], v[5], v[6], v[7]);
                    } else {                           // K|V -> fp16
                        HF8 hf;
#pragma unroll
                        for (int j = 0; j < 8; j++) hf.h[j] = __float2half_rn(v[j]);
                        *(uint4*)(g_kvh + (size_t)row * 256 + (colb - 128)) = hf.u4;
                    }
                } else {
                    if (C) {
                        *(float4*)(C + (size_t)row * ldc + colb)     = make_float4(v[0], v[1], v[2], v[3]);
                        *(float4*)(C + (size_t)row * ldc + colb + 4) = make_float4(v[4], v[5], v[6], v[7]);
                    }
                    if (CH) {
                        BF8 h, l;
#pragma unroll
                        for (int j = 0; j < 8; j++) {
                            bf16 hh = __float2bfloat16(v[j]);
                            h.b[j] = hh;
                            l.b[j] = __float2bfloat16(v[j] - __bfloat162float(hh));
                        }
                        *(uint4*)(CH + (size_t)row * ldc + colb) = h.u4;
                        *(uint4*)(CL + (size_t)row * ldc + colb) = l.u4;
                    }
                }
            }
            if (statsSlot >= 0) {
#pragma unroll
                for (int j = 0; j < 8; j++) {
                    float sv = v[j];
                    float qv = v[j] * v[j];
#pragma unroll
                    for (int m = 2; m <= 16; m <<= 1) {
                        sv += __shfl_xor_sync(0xffffffffu, sv, m);
                        qv += __shfl_xor_sync(0xffffffffu, qv, m);
                    }
                    if (lane < 2) {
                        int cc = wCol + ni * 16 + (lane ? 8 : 0) + j;
                        atomicAdd(&sSum[cc], sv);
                        atomicAdd(&sSq[cc], qv);
                    }
                }
            }
            __syncwarp();
        }

    if (statsSlot >= 0) {
        __syncthreads();
        if (tid < 128)       atomicAdd(&g_red[statsSlot * 128 + tid], sSum[tid]);
        else if (tid < 256)  atomicAdd(&g_red[(statsSlot + 1) * 128 + tid - 128], sSq[tid - 128]);
    }
}

// --------- merged BN1 finalize + W1 fold/split + b1 fold (one kernel) --------
__global__ void k_fin1w1(const float* __restrict__ W1, const float* __restrict__ b1,
                         const float* __restrict__ gam, const float* __restrict__ bet,
                         int n) {
    __shared__ float sc[128], sh[128];
    int t = threadIdx.x;
    if (t < 128) {
        float mean = g_red[t] / (float)n;
        float var  = g_red[128 + t] / (float)n - mean * mean;
        float inv  = rsqrtf(var + 1e-5f);
        float s    = gam[t] * inv;
        sc[t] = s;
        sh[t] = bet[t] - mean * s;
        if (blockIdx.x == 0) { g_aff[t] = s; g_aff[128 + t] = sh[t]; }
    }
    __syncthreads();
    int i = blockIdx.x * 256 + t;
    int k = i >> 8;
    splitw(sc[k] * W1[i], &g_w1h[i], &g_w1l[i]);
    if (blockIdx.x == 0) {
        float s = b1[t];
        for (int kk = 0; kk < 128; kk++) s += sh[kk] * W1[kk * 256 + t];
        g_b1fold[t] = s;
    }
}

// ------------- merged BN2 finalize + apply (grid-stride float4) --------------
__global__ void k_fin2apply(float* __restrict__ out,
                            const float* __restrict__ gam, const float* __restrict__ bet,
                            int n, int total4) {
    __shared__ float sc[128], sh[128];
    int t = threadIdx.x;
    if (t < 128) {
        float mean = g_red[256 + t] / (float)n;
        float var  = g_red[384 + t] / (float)n - mean * mean;
        float inv  = rsqrtf(var + 1e-5f);
        float s    = gam[t] * inv;
        sc[t] = s;
        sh[t] = bet[t] - mean * s;
    }
    __syncthreads();
    for (int i = blockIdx.x * blockDim.x + t; i < total4; i += gridDim.x * blockDim.x) {
        float4 v = *(float4*)(out + (size_t)i * 4);
        int c = (i * 4) & 127;
        v.x = v.x * sc[c]     + sh[c];
        v.y = v.y * sc[c + 1] + sh[c + 1];
        v.z = v.z * sc[c + 2] + sh[c + 2];
        v.w = v.w * sc[c + 3] + sh[c + 3];
        *(float4*)(out + (size_t)i * 4) = v;
    }
}

// ------------------------------- launcher ------------------------------------
extern "C" void kernel_launch(void* const* d_in, const int* in_sizes, int n_in,
                              void* d_out, int out_size) {
    const float* x   = (const float*)d_in[0];
    const void*  ei  = d_in[1];
    const float* WQ  = (const float*)d_in[2];
    const float* WK  = (const float*)d_in[3];
    const float* WV  = (const float*)d_in[4];
    const float* WO  = (const float*)d_in[5];
    const float* bO  = (const float*)d_in[6];
    const float* W1  = (const float*)d_in[7];
    const float* b1  = (const float*)d_in[8];
    const float* W2  = (const float*)d_in[9];
    const float* b2  = (const float*)d_in[10];
    const float* g1v = (const float*)d_in[11];
    const float* be1 = (const float*)d_in[12];
    const float* g2v = (const float*)d_in[13];
    const float* be2 = (const float*)d_in[14];

    int n = in_sizes[0] / 128;
    int e = in_sizes[1] / 2;
    float* out = (float*)d_out;

    int nb = (n + 1023) / 1024;

    // #1: detect + zero (both streams depend on this)
    k_init<<<(n + 255) / 256, 256>>>(ei, e, n);
    cudaEventRecord(g_e1, 0);

    // main stream: merged x-split + weight-split, then QKV GEMM
    k_prep<<<(n * 32 + 255) / 256, 256>>>(x, n * 32, WQ, WK, WV, WO, W2);

    dim3 gQKV((n + 127) / 128, 3);
    dim3 g1g((n + 127) / 128, 1);
    dim3 g2g((n + 127) / 128, 2);

    // QKV: x @ [WQ|WK|WV] -> Q fp32 (g_qf) + K|V fp16 (g_kvh); 2-term split
    pgemm<<<gQKV, 256>>>(0, 8, 384, 0, -1, -1, n, 128, 384,
                         0, -1, 0, -1, 0, 0, -1, 0, -1, 1, 2);

    // fork: CSR build on g_s2, overlapping prep/QKV on main
    cudaStreamWaitEvent(g_s2, g_e1, 0);
    k_hist   <<<(e + 255) / 256, 256, 0, g_s2>>>(ei, e);
    k_scan1  <<<nb, 1024, 0, g_s2>>>(n);
    k_scan2  <<<1, 32, 0, g_s2>>>(nb);
    k_scan3  <<<nb, 1024, 0, g_s2>>>(n, e);
    k_scatter<<<(e + 255) / 256, 256, 0, g_s2>>>(ei, e);
    cudaEventRecord(g_e2, g_s2);
    cudaStreamWaitEvent(0, g_e2, 0);

    // join: attention (needs QKV + CSR)
    k_attn<<<(n + 7) / 8, 256>>>(n);

    // h1 = agg @ WO + bO + x  (BN1 stats fused), 3-term
    pgemm<<<g1g, 256>>>(2, 10, 128, 0, 1, 4, n, 128, 128,
                        bO, -1, x, -1, 1, 128, -1, 0, 0, 0, 3);

    // BN1 finalize + W1 fold/split + b1 fold (one kernel)
    k_fin1w1<<<128, 256>>>(W1, b1, g1v, be1, n);

    // hidden = relu( h1 @ W1' + b1fold ), 3-term
    pgemm<<<g2g, 256>>>(4, 12, 256, 0, -1, 6, n, 128, 256,
                        0, 2, 0, -1, 0, 0, -1, 1, -1, 0, 3);

    // out = hidden @ W2 + b2 + BN1(h1)  (BN2 stats fused), 3-term
    pgemm<<<g1g, 256>>>(6, 14, 128, out, -1, -1, n, 256, 128,
                        b2, -1, 0, 1, 1, 128, 0, 0, 2, 0, 3);

    // BN2 finalize + apply (one kernel)
    k_fin2apply<<<1600, 256>>>(out, g2v, be2, n, n * 32);
}